// round 13
// baseline (speedup 1.0000x reference)
#include <cuda_runtime.h>

// Problem constants (fixed by the reference)
#define BB 16
#define SS 2048
#define HH 1024

#define BLKS_PER_BATCH (SS / 16)   // 128 score blocks per batch row

// Partial folded projection: g_u2p[c][j] = sum over h-chunk c of v[h]*W[h,H+j].
// Written with plain stores every call (no zero-invariant needed).
__device__ float g_u2p[8][HH];
// Tail counters. Invariant: zero at entry (module-load zero; final tail resets).
__device__ int g_cnt[BB];
__device__ int g_batches;

// ---------------------------------------------------------------------------
// Kernel 1: partial u2 = v^T @ attn_w[:, H:2H], split over columns AND rows.
// grid (32, 8): blockIdx.x = 32-column tile, blockIdx.y = 128-row chunk.
// Warp w covers rows {h0+w, h0+w+8, ...}; lane <-> column: every load is a
// fully-used coalesced 128B line, 16 independent loads in flight per warp.
// ---------------------------------------------------------------------------
__global__ __launch_bounds__(256) void u2_kernel(
    const float* __restrict__ attn_w,  // [H, 2H] row-major
    const float* __restrict__ v)       // [1, H]
{
    __shared__ float part[8][32];
    const int warp = threadIdx.x >> 5;   // 0..7
    const int lane = threadIdx.x & 31;
    const int j0 = blockIdx.x * 32;      // column tile base
    const int h0 = blockIdx.y * 128;     // row chunk base

    const float* base = attn_w + HH + j0 + lane;   // &W[0, H+j0+lane]
    float acc = 0.f;
#pragma unroll
    for (int i = 0; i < 16; ++i) {
        const int h = h0 + warp + i * 8;
        acc += __ldg(v + h) * __ldg(base + (size_t)h * (2 * HH));
    }
    part[warp][lane] = acc;
    __syncthreads();

    if (threadIdx.x < 32) {
        float s = 0.f;
#pragma unroll
        for (int w = 0; w < 8; ++w) s += part[w][threadIdx.x];
        g_u2p[blockIdx.y][j0 + threadIdx.x] = s;
    }
}

// ---------------------------------------------------------------------------
// Kernel 2: scores + tail-fused softmax.
// grid 2048 x 512. Each block: stage u2 (sum of 8 partials, 4KB smem), dot 16
// enc rows (streaming float4), write scores (__stcg). The 128th block to
// finish in each batch (atomic counter) runs that batch's softmax from
// L2-hot scores; the 16th batch-tail resets the counters for graph replay.
// ---------------------------------------------------------------------------
__global__ __launch_bounds__(512) void scores_kernel(
    const float* __restrict__ enc,    // [B, S, H]
    float* __restrict__ out)          // [B*S] scores -> softmax probs
{
    __shared__ float4 su2[HH / 4];    // 4 KB
    __shared__ float  red[16];
    __shared__ int    s_last, s_final;

    const int tid  = threadIdx.x;
    const int warp = tid >> 5;
    const int lane = tid & 31;
    const int bid  = blockIdx.x;

    if (tid < HH / 4) {
        const float4* p = reinterpret_cast<const float4*>(g_u2p);  // [8][256]
        float4 a = p[tid];
#pragma unroll
        for (int c = 1; c < 8; ++c) {
            const float4 b = p[c * (HH / 4) + tid];
            a.x += b.x; a.y += b.y; a.z += b.z; a.w += b.w;
        }
        su2[tid] = a;
    }
    __syncthreads();

    const int row = bid * 16 + warp;      // 0 .. B*S-1
    const float4* e = reinterpret_cast<const float4*>(enc) + (size_t)row * (HH / 4);

    float acc = 0.f;
#pragma unroll
    for (int it = 0; it < 8; ++it) {
        const float4 ev = __ldcs(e + it * 32 + lane);   // streaming: no reuse
        const float4 uv = su2[it * 32 + lane];
        acc += ev.x * uv.x + ev.y * uv.y + ev.z * uv.z + ev.w * uv.w;
    }
#pragma unroll
    for (int m = 16; m; m >>= 1)
        acc += __shfl_xor_sync(0xffffffffu, acc, m);
    if (lane == 0) __stcg(out + row, acc);

    // ---- tail election: last block of this batch runs the softmax ----
    const int batch = bid >> 7;           // 128 blocks per batch
    __syncthreads();                      // all score stores program-ordered before tid0
    if (tid == 0) {
        __threadfence();                  // release this block's score writes
        s_last = (atomicAdd(&g_cnt[batch], 1) == BLKS_PER_BATCH - 1);
        if (s_last) __threadfence();      // acquire: order score reads after counter
    }
    __syncthreads();
    if (!s_last) return;

    // ---- softmax over this batch's 2048 scores (512 threads x float4) ----
    float4* po = reinterpret_cast<float4*>(out + (size_t)batch * SS);
    float4 x = __ldcg(po + tid);

    float mx = fmaxf(fmaxf(x.x, x.y), fmaxf(x.z, x.w));
#pragma unroll
    for (int m = 16; m; m >>= 1)
        mx = fmaxf(mx, __shfl_xor_sync(0xffffffffu, mx, m));
    if (lane == 0) red[warp] = mx;
    __syncthreads();
    float bmax = red[0];
#pragma unroll
    for (int w = 1; w < 16; ++w) bmax = fmaxf(bmax, red[w]);
    __syncthreads();

    x.x = __expf(x.x - bmax); x.y = __expf(x.y - bmax);
    x.z = __expf(x.z - bmax); x.w = __expf(x.w - bmax);
    float s = x.x + x.y + x.z + x.w;
#pragma unroll
    for (int m = 16; m; m >>= 1)
        s += __shfl_xor_sync(0xffffffffu, s, m);
    if (lane == 0) red[warp] = s;
    __syncthreads();
    float tot = 0.f;
#pragma unroll
    for (int w = 0; w < 16; ++w) tot += red[w];
    const float inv = 1.0f / tot;
    x.x *= inv; x.y *= inv; x.z *= inv; x.w *= inv;
    po[tid] = x;

    // ---- cleanup: the 16th (final) batch-tail restores the counters ----
    __syncthreads();
    if (tid == 0)
        s_final = (atomicAdd(&g_batches, 1) == BB - 1);
    __syncthreads();
    if (s_final) {
        if (tid < BB) g_cnt[tid] = 0;
        if (tid == 0) g_batches = 0;
    }
}

// ---------------------------------------------------------------------------
// Inputs (metadata order): hidden [B,1,H], encoder_outputs [B,S,H],
//                          attn_w [H,2H], attn_b [H], v [1,H]
// hidden and attn_b are provably unused (softmax shift invariance folds them
// into a per-row constant).
// Output: [B,1,S] float32.
// ---------------------------------------------------------------------------
extern "C" void kernel_launch(void* const* d_in, const int* in_sizes, int n_in,
                              void* d_out, int out_size)
{
    const float* enc    = (const float*)d_in[1];
    const float* attn_w = (const float*)d_in[2];
    const float* v      = (const float*)d_in[4];
    float* out = (float*)d_out;

    dim3 g1(HH / 32, 8);
    u2_kernel<<<g1, 256>>>(attn_w, v);
    scores_kernel<<<(BB * SS) / 16, 512>>>(enc, out);
}

// round 16
// speedup vs baseline: 1.2455x; 1.2455x over previous
#include <cuda_runtime.h>

// Problem constants (fixed by the reference)
#define BB 16
#define SS 2048
#define HH 1024

// Folded projection vector u2[j] = sum_h v[h] * attn_w[h, H+j].
// Invariant: zero at entry of every kernel_launch call (module-load zero;
// softmax_kernel block 0 re-zeroes it at the end of every call).
__device__ float g_u2[HH];

// ---------------------------------------------------------------------------
// Kernel 1: u2 += v^T @ attn_w[:, H:2H], maximum memory-level parallelism.
// grid (8, 128) = 1024 blocks x 256 threads; block = 128-col tile x 8 rows.
// Each thread issues exactly ONE coalesced float4 load (warp w -> row h0+w,
// lane -> 16B column chunk), so the whole 4 MB is in flight at once across
// ~7 blocks/SM. Block reduces 8 rows in smem; warp 0 atomicAdds 128 floats
// (128 adds per g_u2 address chip-wide, spread over block completions).
// ---------------------------------------------------------------------------
__global__ __launch_bounds__(256) void u2_kernel(
    const float* __restrict__ attn_w,  // [H, 2H] row-major
    const float* __restrict__ v)       // [1, H]
{
    __shared__ float4 part[8][32];
    const int warp = threadIdx.x >> 5;   // 0..7
    const int lane = threadIdx.x & 31;
    const int j0 = blockIdx.x * 128;     // column tile base (32 lanes x float4)
    const int h  = blockIdx.y * 8 + warp;

    const float4 w4 = __ldg(reinterpret_cast<const float4*>(attn_w + (size_t)h * (2 * HH) + HH + j0) + lane);
    const float vv = __ldg(v + h);
    part[warp][lane] = make_float4(vv * w4.x, vv * w4.y, vv * w4.z, vv * w4.w);
    __syncthreads();

    if (warp == 0) {
        float4 s = part[0][lane];
#pragma unroll
        for (int w = 1; w < 8; ++w) {
            const float4 p = part[w][lane];
            s.x += p.x; s.y += p.y; s.z += p.z; s.w += p.w;
        }
        float* dst = g_u2 + j0 + lane * 4;
        atomicAdd(dst + 0, s.x);
        atomicAdd(dst + 1, s.y);
        atomicAdd(dst + 2, s.z);
        atomicAdd(dst + 3, s.w);
    }
}

// ---------------------------------------------------------------------------
// Kernel 2: scores[row] = enc[row, :] . u2   (exact R7 structure, 6.7 TB/s)
// 512 threads = 16 warps, warp-per-row; u2 staged once per block (4 KB).
// Streaming float4 loads on the 128 MB encoder tensor. No fences, no tails.
// ---------------------------------------------------------------------------
__global__ __launch_bounds__(512) void scores_kernel(
    const float* __restrict__ enc,    // [B, S, H]
    float* __restrict__ out)          // [B*S] scores (in d_out)
{
    __shared__ float4 su2[HH / 4];    // 4 KB
    if (threadIdx.x < HH / 4)
        su2[threadIdx.x] = reinterpret_cast<const float4*>(g_u2)[threadIdx.x];
    __syncthreads();

    const int warp = threadIdx.x >> 5;
    const int lane = threadIdx.x & 31;
    const int row  = blockIdx.x * 16 + warp;      // 0 .. B*S-1

    const float4* e = reinterpret_cast<const float4*>(enc) + (size_t)row * (HH / 4);

    float acc = 0.f;
#pragma unroll
    for (int it = 0; it < 8; ++it) {
        const float4 ev = __ldcs(e + it * 32 + lane);   // streaming: no reuse
        const float4 uv = su2[it * 32 + lane];
        acc += ev.x * uv.x + ev.y * uv.y + ev.z * uv.z + ev.w * uv.w;
    }
#pragma unroll
    for (int m = 16; m; m >>= 1)
        acc += __shfl_xor_sync(0xffffffffu, acc, m);
    if (lane == 0) out[row] = acc;
}

// ---------------------------------------------------------------------------
// Kernel 3: in-place row softmax over S=2048, one block per batch row.
// 1024 threads x float2: minimal dependent chain per thread.
// Block 0 also restores the g_u2 == 0 invariant for the next graph replay.
// ---------------------------------------------------------------------------
__global__ __launch_bounds__(1024) void softmax_kernel(float* __restrict__ out)
{
    __shared__ float red[32];
    const int tid  = threadIdx.x;
    const int warp = tid >> 5;           // 0..31
    const int lane = tid & 31;

    // Reset g_u2 for the next call (safe: u2's atomics finished last launch).
    if (blockIdx.x == 0 && tid < HH / 4)
        reinterpret_cast<float4*>(g_u2)[tid] = make_float4(0.f, 0.f, 0.f, 0.f);

    float2* po = reinterpret_cast<float2*>(out + (size_t)blockIdx.x * SS);
    float2 x = po[tid];

    // ---- block max ----
    float mx = fmaxf(x.x, x.y);
#pragma unroll
    for (int m = 16; m; m >>= 1)
        mx = fmaxf(mx, __shfl_xor_sync(0xffffffffu, mx, m));
    if (lane == 0) red[warp] = mx;
    __syncthreads();
    if (warp == 0) {
        float t = red[lane];
#pragma unroll
        for (int m = 16; m; m >>= 1)
            t = fmaxf(t, __shfl_xor_sync(0xffffffffu, t, m));
        red[lane] = t;                    // all 32 entries = block max
    }
    __syncthreads();
    const float bmax = red[0];

    // ---- exp + block sum ----
    x.x = __expf(x.x - bmax);
    x.y = __expf(x.y - bmax);
    float s = x.x + x.y;
#pragma unroll
    for (int m = 16; m; m >>= 1)
        s += __shfl_xor_sync(0xffffffffu, s, m);
    __syncthreads();                      // red reuse safe
    if (lane == 0) red[warp] = s;
    __syncthreads();
    if (warp == 0) {
        float t = red[lane];
#pragma unroll
        for (int m = 16; m; m >>= 1)
            t += __shfl_xor_sync(0xffffffffu, t, m);
        red[lane] = t;
    }
    __syncthreads();
    const float inv = 1.0f / red[0];

    x.x *= inv; x.y *= inv;
    po[tid] = x;
}

// ---------------------------------------------------------------------------
// Inputs (metadata order): hidden [B,1,H], encoder_outputs [B,S,H],
//                          attn_w [H,2H], attn_b [H], v [1,H]
// hidden and attn_b are provably unused (softmax shift invariance folds them
// into a per-row constant).
// Output: [B,1,S] float32.
// ---------------------------------------------------------------------------
extern "C" void kernel_launch(void* const* d_in, const int* in_sizes, int n_in,
                              void* d_out, int out_size)
{
    const float* enc    = (const float*)d_in[1];
    const float* attn_w = (const float*)d_in[2];
    const float* v      = (const float*)d_in[4];
    float* out = (float*)d_out;

    dim3 g1(HH / 128, 128);
    u2_kernel<<<g1, 256>>>(attn_w, v);
    scores_kernel<<<(BB * SS) / 16, 512>>>(enc, out);
    softmax_kernel<<<BB, 1024>>>(out);
}